// round 15
// baseline (speedup 1.0000x reference)
#include <cuda_runtime.h>
#include <cuda_fp16.h>
#include <math.h>
#include <stdint.h>

// Problem constants
#define BSZ 2
#define NT  128
#define DM  512
#define NH  8
#define DHD 64
#define HIDD 2048
#define EPSC 1e-5f

#define HTOT (BSZ*NT*DM)                 // 131072
#define EROWS (BSZ*NT*NT)                // 32768
#define EHALF (EROWS/2)                  // 16384 (one batch)
#define ETOT ((size_t)EROWS*DM)          // 16777216
#define QKVW 2560
#define WPOOL 8388608

typedef __half HT;

// ---------------- scratch (static device allocations) ----------------
__device__ float g_h1[HTOT];
__device__ float g_h2[HTOT];
__device__ float g_qkv[BSZ*NT*QKVW];
__device__ float g_scale[DM], g_shift[DM];
__device__ float g_pS[64][DM], g_pQ[64][DM];

__device__ HT g_e1hi[(size_t)EROWS*DM];
__device__ HT g_e2hi[(size_t)EROWS*DM];
__device__ HT g_evhi[(size_t)EROWS*DM];
__device__ HT g_Shi[(size_t)EROWS*HIDD];
__device__ HT g_h1hi[HTOT];
__device__ HT g_aohi[HTOT];
__device__ HT g_xhhi[HTOT];
__device__ HT g_shhi[BSZ*NT*HIDD];
__device__ HT g_whi[WPOOL];

// ---------------- helpers ----------------
__device__ __forceinline__ uint32_t smem_u32(const void* p) {
    uint32_t a;
    asm("{ .reg .u64 t; cvta.to.shared.u64 t, %1; cvt.u32.u64 %0, t; }" : "=r"(a) : "l"(p));
    return a;
}
__device__ __forceinline__ void ldsm_x4(uint32_t* r, uint32_t addr) {
    asm volatile("ldmatrix.sync.aligned.m8n8.x4.shared.b16 {%0,%1,%2,%3}, [%4];"
                 : "=r"(r[0]), "=r"(r[1]), "=r"(r[2]), "=r"(r[3]) : "r"(addr));
}
__device__ __forceinline__ void mma_fp16(float* d, const uint32_t* a, uint32_t b0, uint32_t b1) {
    asm volatile(
        "mma.sync.aligned.m16n8k16.row.col.f32.f16.f16.f32 "
        "{%0,%1,%2,%3}, {%4,%5,%6,%7}, {%8,%9}, {%0,%1,%2,%3};"
        : "+f"(d[0]), "+f"(d[1]), "+f"(d[2]), "+f"(d[3])
        : "r"(a[0]), "r"(a[1]), "r"(a[2]), "r"(a[3]), "r"(b0), "r"(b1));
}
__device__ __forceinline__ void cvt4_hi(const float4& o, HT* hi) {
    __half2 p01 = __floats2half2_rn(o.x, o.y);
    __half2 p23 = __floats2half2_rn(o.z, o.w);
    uint2 hv;
    hv.x = *(uint32_t*)&p01;
    hv.y = *(uint32_t*)&p23;
    *(uint2*)hi = hv;
}
__device__ __forceinline__ float2 h2f2(const HT* p) {
    __half2 h = *(const __half2*)p;
    return __half22float2(h);
}

// ---------------- mma.sync GEMM: C[M,N] = sum_k A[M,K]*B[N,K]  (B is W^T) ----------------
// pure fp16 operands, fp32 accumulate, single pass.
// BM=BN=128, BK=32, 256 threads (8 warps: 4 m x 2 n), warp tile 32x64,
// LDG-prefetch double buffer, ONE __syncthreads per K-iter.
// MODE 0: C = acc (+bias)(+add fp32)(+addh fp16), fp32 out
// MODE 1: v = acc + aux1[(row>>7)*aS+col] + aux2[((row>>14)*128+(row&127))*aS+col] -> Ohi fp16
//         (rows may be batch-local with per-batch aux base pointers)
// MODE 2: interleaved (u,t) col pairs; silu(u)*t -> Ohi fp16 at [row, col/2] (staged)
// MODE 3: v = acc + bias + addh(fp16) -> Ohi fp16 (staged)
#define PADR 40   // smem row stride in fp16 elements (80 bytes)

template<int MODE>
__global__ __launch_bounds__(256, 2) void tc_gemm(
    const HT* __restrict__ Ahi, const HT* __restrict__ Bhi,
    float* __restrict__ C, int M, int N, int K,
    const float* __restrict__ bias, const float* __restrict__ add,
    const HT* __restrict__ addh,
    HT* __restrict__ Ohi,
    const float* __restrict__ aux1, const float* __restrict__ aux2, int aS)
{
    __shared__ __align__(16) HT sA[2][128 * PADR];
    __shared__ __align__(16) HT sB[2][128 * PADR];

    const int tid = threadIdx.x, lane = tid & 31, wid = tid >> 5;
    const int warp_m = wid & 3, warp_n = wid >> 2;
    const int m0 = blockIdx.y * 128, n0 = blockIdx.x * 128;
    const int total = K >> 5;

    const int lr = tid >> 2;     // 0..63
    const int lg = tid & 3;      // k-group of 8

    float acc[2][8][4];
    #pragma unroll
    for (int s = 0; s < 2; s++)
        #pragma unroll
        for (int f = 0; f < 8; f++)
            #pragma unroll
            for (int u = 0; u < 4; u++) acc[s][f][u] = 0.f;

    uint4 pa[2], pb[2];
    auto LOADREGS = [&](int it) {
        const HT* ab = Ahi + (size_t)(m0 + lr) * K + it * 32 + lg * 8;
        pa[0] = *(const uint4*)ab;
        pa[1] = *(const uint4*)(ab + (size_t)64 * K);
        const HT* bb = Bhi + (size_t)(n0 + lr) * K + it * 32 + lg * 8;
        pb[0] = *(const uint4*)bb;
        pb[1] = *(const uint4*)(bb + (size_t)64 * K);
    };
    auto STORESM = [&](int buf) {
        *(uint4*)&sA[buf][lr * PADR + lg * 8] = pa[0];
        *(uint4*)&sA[buf][(lr + 64) * PADR + lg * 8] = pa[1];
        *(uint4*)&sB[buf][lr * PADR + lg * 8] = pb[0];
        *(uint4*)&sB[buf][(lr + 64) * PADR + lg * 8] = pb[1];
    };

    const uint32_t aBase = smem_u32(&sA[0][0]);
    const uint32_t bBase = smem_u32(&sB[0][0]);
    const uint32_t BUFB = 128 * PADR * 2;
    const uint32_t aoff = ((warp_m * 32 + (lane & 15)) * PADR + (lane >> 4) * 8) * 2;
    const uint32_t boff = ((warp_n * 64 + (lane & 15)) * PADR + (lane >> 4) * 8) * 2;

    LOADREGS(0);
    STORESM(0);
    __syncthreads();

    for (int it = 0; it < total; ++it) {
        const int buf = it & 1;
        if (it + 1 < total) LOADREGS(it + 1);

        const uint32_t ab = aBase + buf * BUFB + aoff;
        const uint32_t bb = bBase + buf * BUFB + boff;
        #pragma unroll
        for (int kk = 0; kk < 32; kk += 16) {
            uint32_t A0[4], A1[4], Bf[4][4];
            ldsm_x4(A0, ab + kk * 2);
            ldsm_x4(A1, ab + kk * 2 + 16 * PADR * 2);
            #pragma unroll
            for (int g = 0; g < 4; g++) ldsm_x4(Bf[g], bb + kk * 2 + g * 16 * PADR * 2);
            #pragma unroll
            for (int fn = 0; fn < 8; fn++) {
                uint32_t b0 = Bf[fn >> 1][fn & 1];
                uint32_t b1 = Bf[fn >> 1][(fn & 1) + 2];
                mma_fp16(acc[0][fn], A0, b0, b1);
                mma_fp16(acc[1][fn], A1, b0, b1);
            }
        }
        // One barrier per iteration: STS targets the buffer whose readers
        // finished before the PREVIOUS barrier.
        if (it + 1 < total) STORESM(buf ^ 1);
        __syncthreads();
    }

    if (MODE == 0) {
        #pragma unroll
        for (int s = 0; s < 2; s++) {
            int ra = m0 + warp_m * 32 + s * 16 + (lane >> 2);
            int rb = ra + 8;
            #pragma unroll
            for (int fn = 0; fn < 8; fn++) {
                int cb = n0 + warp_n * 64 + fn * 8 + (lane & 3) * 2;
                float2 v0 = {acc[s][fn][0], acc[s][fn][1]};
                float2 v1 = {acc[s][fn][2], acc[s][fn][3]};
                if (bias) {
                    float2 bv = *(const float2*)(bias + cb);
                    v0.x += bv.x; v0.y += bv.y;
                    v1.x += bv.x; v1.y += bv.y;
                }
                if (add) {
                    float2 a0 = *(const float2*)(add + (size_t)ra * N + cb);
                    float2 a1 = *(const float2*)(add + (size_t)rb * N + cb);
                    v0.x += a0.x; v0.y += a0.y;
                    v1.x += a1.x; v1.y += a1.y;
                }
                if (addh) {
                    float2 a0 = h2f2(addh + (size_t)ra * N + cb);
                    float2 a1 = h2f2(addh + (size_t)rb * N + cb);
                    v0.x += a0.x; v0.y += a0.y;
                    v1.x += a1.x; v1.y += a1.y;
                }
                *(float2*)(C + (size_t)ra * N + cb) = v0;
                *(float2*)(C + (size_t)rb * N + cb) = v1;
            }
        }
    } else if (MODE == 1 || MODE == 3) {
        // stage fp16 (16 rows x 64 cols per warp, row stride 72)
        HT* stg = &sA[0][0] + wid * (16 * 72);
        #pragma unroll
        for (int s = 0; s < 2; s++) {
            int ra = m0 + warp_m * 32 + s * 16 + (lane >> 2);
            int rb = ra + 8;
            const float* a1rA = (MODE == 1) ? aux1 + (size_t)(ra >> 7) * aS : nullptr;
            const float* a2rA = (MODE == 1) ? aux2 + ((size_t)(ra >> 14) * 128 + (ra & 127)) * aS : nullptr;
            const float* a2rB = (MODE == 1) ? aux2 + ((size_t)(rb >> 14) * 128 + (rb & 127)) * aS : nullptr;
            #pragma unroll
            for (int fn = 0; fn < 8; fn++) {
                int cb = n0 + warp_n * 64 + fn * 8 + (lane & 3) * 2;
                float2 v0 = {acc[s][fn][0], acc[s][fn][1]};
                float2 v1 = {acc[s][fn][2], acc[s][fn][3]};
                if (MODE == 1) {
                    float2 x1 = *(const float2*)(a1rA + cb);
                    float2 xa = *(const float2*)(a2rA + cb);
                    float2 xb = *(const float2*)(a2rB + cb);
                    v0.x += x1.x + xa.x; v0.y += x1.y + xa.y;
                    v1.x += x1.x + xb.x; v1.y += x1.y + xb.y;
                } else {
                    if (bias) {
                        float2 bv = *(const float2*)(bias + cb);
                        v0.x += bv.x; v0.y += bv.y;
                        v1.x += bv.x; v1.y += bv.y;
                    }
                    float2 a0 = h2f2(addh + (size_t)ra * N + cb);
                    float2 a1 = h2f2(addh + (size_t)rb * N + cb);
                    v0.x += a0.x; v0.y += a0.y;
                    v1.x += a1.x; v1.y += a1.y;
                }
                int c0 = fn * 8 + (lane & 3) * 2;
                __half2 h0 = __floats2half2_rn(v0.x, v0.y);
                __half2 h1 = __floats2half2_rn(v1.x, v1.y);
                *(__half2*)&stg[(lane >> 2) * 72 + c0] = h0;
                *(__half2*)&stg[((lane >> 2) + 8) * 72 + c0] = h1;
            }
            __syncwarp();
            {
                int row = lane >> 1, half = lane & 1;
                const uint4* src = (const uint4*)&stg[row * 72 + half * 32];
                int grow = m0 + warp_m * 32 + s * 16 + row;
                uint4* dst = (uint4*)(Ohi + (size_t)grow * N + n0 + warp_n * 64 + half * 32);
                dst[0] = src[0]; dst[1] = src[1]; dst[2] = src[2]; dst[3] = src[3];
            }
            __syncwarp();
        }
    } else {  // MODE 2
        HT* stg = &sA[0][0] + wid * (16 * 40);
        const int NS = N >> 1;
        #pragma unroll
        for (int s = 0; s < 2; s++) {
            #pragma unroll
            for (int fn = 0; fn < 8; fn++) {
                float u0 = acc[s][fn][0], t0 = acc[s][fn][1];
                float u1 = acc[s][fn][2], t1 = acc[s][fn][3];
                float s0 = u0 / (1.f + expf(-u0)) * t0;
                float s1 = u1 / (1.f + expf(-u1)) * t1;
                int c = fn * 4 + (lane & 3);
                stg[(lane >> 2) * 40 + c] = __float2half_rn(s0);
                stg[((lane >> 2) + 8) * 40 + c] = __float2half_rn(s1);
            }
            __syncwarp();
            {
                int row = lane >> 1, half = lane & 1;
                const uint4* src = (const uint4*)&stg[row * 40 + half * 16];
                int grow = m0 + warp_m * 32 + s * 16 + row;
                uint4* dst = (uint4*)(Ohi + (size_t)grow * NS + (n0 >> 1) + warp_n * 32 + half * 16);
                dst[0] = src[0]; dst[1] = src[1];
            }
            __syncwarp();
        }
    }
}

// ---------------- batched weight transpose: w[K,N] fp32 -> hi fp16 ----------------
struct WPtr8 { const float* p[8]; };

__global__ void wcvt8(WPtr8 wb, HT* __restrict__ hi) {
    __shared__ float t[32][33];
    int z = blockIdx.z;
    const float* w = wb.p[z];
    HT* dst = hi + (size_t)z * 262144;
    int kb = blockIdx.y * 32, nb = blockIdx.x * 32;
    int tx = threadIdx.x, ty = threadIdx.y;  // 32x8
    #pragma unroll
    for (int i = 0; i < 32; i += 8)
        t[ty + i][tx] = w[(size_t)(kb + ty + i) * 512 + nb + tx];
    __syncthreads();
    #pragma unroll
    for (int i = 0; i < 32; i += 8)
        dst[(size_t)(nb + ty + i) * 512 + kb + tx] = __float2half_rn(t[tx][ty + i]);
}

struct WPtr4 { const float* p[4]; };
__global__ void wcvt13(WPtr4 wb, HT* __restrict__ hiA, HT* __restrict__ hiB) {
    __shared__ float t[32][33];
    int z = blockIdx.z;
    const float* w = wb.p[z];
    HT* dst = (z < 2) ? hiA : hiB;
    int ofs = z & 1;
    int kb = blockIdx.y * 32, nb = blockIdx.x * 32;
    int tx = threadIdx.x, ty = threadIdx.y;
    #pragma unroll
    for (int i = 0; i < 32; i += 8)
        t[ty + i][tx] = w[(size_t)(kb + ty + i) * 2048 + nb + tx];
    __syncthreads();
    #pragma unroll
    for (int i = 0; i < 32; i += 8)
        dst[((size_t)(nb + ty + i) * 2 + ofs) * 512 + kb + tx] = __float2half_rn(t[tx][ty + i]);
}

__global__ void wcvt2(const float* __restrict__ wa, const float* __restrict__ wb,
                      HT* __restrict__ hiA, HT* __restrict__ hiB) {
    __shared__ float t[32][33];
    int z = blockIdx.z;
    const float* w = z ? wb : wa;
    HT* dst = z ? hiB : hiA;
    int kb = blockIdx.y * 32, nb = blockIdx.x * 32;
    int tx = threadIdx.x, ty = threadIdx.y;
    #pragma unroll
    for (int i = 0; i < 32; i += 8)
        t[ty + i][tx] = w[(size_t)(kb + ty + i) * 512 + nb + tx];
    __syncthreads();
    #pragma unroll
    for (int i = 0; i < 32; i += 8)
        dst[(size_t)(nb + ty + i) * 2048 + kb + tx] = __float2half_rn(t[tx][ty + i]);
}

// ---------------- BatchNorm: two-phase parallel stats ----------------
__global__ void bn_part(const float* __restrict__ x) {
    int blk = blockIdx.x;
    int t = threadIdx.x;
    int c = t * 2;
    float s0 = 0.f, s1 = 0.f, q0 = 0.f, q1 = 0.f;
    #pragma unroll
    for (int r = 0; r < 4; r++) {
        float2 v = *(const float2*)(x + (size_t)(blk * 4 + r) * DM + c);
        s0 += v.x; s1 += v.y;
        q0 = fmaf(v.x, v.x, q0); q1 = fmaf(v.y, v.y, q1);
    }
    g_pS[blk][c] = s0; g_pS[blk][c + 1] = s1;
    g_pQ[blk][c] = q0; g_pQ[blk][c + 1] = q1;
}

// 16 blocks x 256 threads: 8 threads per channel, tree reduce
__global__ void bn_fin(const float* __restrict__ g, const float* __restrict__ b) {
    int tid = threadIdx.x;
    int c = blockIdx.x * 32 + (tid >> 3);
    int slot = tid & 7;
    float s = 0.f, q = 0.f;
    #pragma unroll
    for (int t = 0; t < 8; t++) { s += g_pS[slot + 8 * t][c]; q += g_pQ[slot + 8 * t][c]; }
    #pragma unroll
    for (int o = 4; o; o >>= 1) {
        s += __shfl_xor_sync(0xffffffffu, s, o);
        q += __shfl_xor_sync(0xffffffffu, q, o);
    }
    if (slot == 0) {
        const float inv = 1.f / (BSZ * NT);
        float m = s * inv;
        float var = q * inv - m * m;
        float sc = g[c] / sqrtf(var + EPSC);
        g_scale[c] = sc;
        g_shift[c] = b[c] - m * sc;
    }
}

__global__ void bn_apply_cvt(const float* __restrict__ x, float* __restrict__ y,
                             HT* __restrict__ hi) {
    int i = blockIdx.x * blockDim.x + threadIdx.x;
    if (i >= HTOT / 4) return;
    int idx = i * 4;
    int c = idx & (DM - 1);
    float4 v = *(const float4*)(x + idx);
    float4 o;
    o.x = fmaf(v.x, g_scale[c + 0], g_shift[c + 0]);
    o.y = fmaf(v.y, g_scale[c + 1], g_shift[c + 1]);
    o.z = fmaf(v.z, g_scale[c + 2], g_shift[c + 2]);
    o.w = fmaf(v.w, g_scale[c + 3], g_shift[c + 3]);
    if (y) *(float4*)(y + idx) = o;
    cvt4_hi(o, hi + idx);
}

// ---------------- LayerNorm, fp32 in -> fp16 hi ----------------
__global__ void ln_cvt(const float* __restrict__ x, HT* __restrict__ hi,
                       const float* __restrict__ g, const float* __restrict__ b) {
    int row = blockIdx.x;
    int t = threadIdx.x;
    float4 v = ((const float4*)(x + (size_t)row * DM))[t];
    float s  = v.x + v.y + v.z + v.w;
    float s2 = fmaf(v.x, v.x, fmaf(v.y, v.y, fmaf(v.z, v.z, v.w * v.w)));
    #pragma unroll
    for (int o = 16; o; o >>= 1) {
        s  += __shfl_xor_sync(0xffffffffu, s,  o);
        s2 += __shfl_xor_sync(0xffffffffu, s2, o);
    }
    __shared__ float sa[4], sbx[4];
    if ((t & 31) == 0) { sa[t >> 5] = s; sbx[t >> 5] = s2; }
    __syncthreads();
    s  = sa[0] + sa[1] + sa[2] + sa[3];
    s2 = sbx[0] + sbx[1] + sbx[2] + sbx[3];
    const float inv = 1.f / DM;
    float m  = s * inv;
    float var = s2 * inv - m * m;
    float rs = rsqrtf(var + EPSC);
    float4 gg = ((const float4*)g)[t];
    float4 bb = ((const float4*)b)[t];
    float4 o;
    o.x = fmaf((v.x - m) * rs, gg.x, bb.x);
    o.y = fmaf((v.y - m) * rs, gg.y, bb.y);
    o.z = fmaf((v.z - m) * rs, gg.z, bb.z);
    o.w = fmaf((v.w - m) * rs, gg.w, bb.w);
    cvt4_hi(o, hi + (size_t)row * DM + t * 4);
}

// ---------------- LayerNorm, fp16 in -> fp16 hi ----------------
__global__ void ln_cvt_h(const HT* __restrict__ x, HT* __restrict__ hi,
                         const float* __restrict__ g, const float* __restrict__ b) {
    int row = blockIdx.x;
    int t = threadIdx.x;
    uint2 raw = ((const uint2*)(x + (size_t)row * DM))[t];
    float2 f01 = __half22float2(*(__half2*)&raw.x);
    float2 f23 = __half22float2(*(__half2*)&raw.y);
    float4 v = {f01.x, f01.y, f23.x, f23.y};
    float s  = v.x + v.y + v.z + v.w;
    float s2 = fmaf(v.x, v.x, fmaf(v.y, v.y, fmaf(v.z, v.z, v.w * v.w)));
    #pragma unroll
    for (int o = 16; o; o >>= 1) {
        s  += __shfl_xor_sync(0xffffffffu, s,  o);
        s2 += __shfl_xor_sync(0xffffffffu, s2, o);
    }
    __shared__ float sa[4], sbx[4];
    if ((t & 31) == 0) { sa[t >> 5] = s; sbx[t >> 5] = s2; }
    __syncthreads();
    s  = sa[0] + sa[1] + sa[2] + sa[3];
    s2 = sbx[0] + sbx[1] + sbx[2] + sbx[3];
    const float inv = 1.f / DM;
    float m  = s * inv;
    float var = s2 * inv - m * m;
    float rs = rsqrtf(var + EPSC);
    float4 gg = ((const float4*)g)[t];
    float4 bb = ((const float4*)b)[t];
    float4 o;
    o.x = fmaf((v.x - m) * rs, gg.x, bb.x);
    o.y = fmaf((v.y - m) * rs, gg.y, bb.y);
    o.z = fmaf((v.z - m) * rs, gg.z, bb.z);
    o.w = fmaf((v.w - m) * rs, gg.w, bb.w);
    cvt4_hi(o, hi + (size_t)row * DM + t * 4);
}

// ---------------- attention: one block per (b,h,i), 128 threads, fp16 out ----------------
__global__ void attn_kernel() {
    int i = blockIdx.x % NT;
    int h = (blockIdx.x / NT) % NH;
    int b = blockIdx.x / (NT * NH);
    int t = threadIdx.x;
    __shared__ float qs[DHD];
    __shared__ float scs[NT];
    __shared__ float red[4];

    if (t < DHD) qs[t] = g_qkv[(size_t)(b * NT + i) * QKVW + h * DHD + t];
    __syncthreads();

    const HT* evrow = g_evhi + ((size_t)(b * NT + i) * NT + t) * DM + h * DHD;
    const float* krow = g_qkv + (size_t)(b * NT + t) * QKVW + DM + h * DHD;
    float s = 0.f;
    #pragma unroll 8
    for (int d = 0; d < DHD; d++)
        s = fmaf(qs[d] * __half2float(evrow[d]), krow[d], s);
    s *= 0.125f;

    float m = s;
    #pragma unroll
    for (int o = 16; o; o >>= 1) m = fmaxf(m, __shfl_xor_sync(0xffffffffu, m, o));
    if ((t & 31) == 0) red[t >> 5] = m;
    __syncthreads();
    m = fmaxf(fmaxf(red[0], red[1]), fmaxf(red[2], red[3]));
    float p = expf(s - m);
    float ssum = p;
    #pragma unroll
    for (int o = 16; o; o >>= 1) ssum += __shfl_xor_sync(0xffffffffu, ssum, o);
    __syncthreads();
    if ((t & 31) == 0) red[t >> 5] = ssum;
    __syncthreads();
    ssum = red[0] + red[1] + red[2] + red[3];
    scs[t] = p / ssum;
    __syncthreads();

    if (t < DHD) {
        float o = 0.f;
        #pragma unroll 8
        for (int j = 0; j < NT; j++)
            o = fmaf(scs[j], g_qkv[(size_t)(b * NT + j) * QKVW + 2 * DM + h * DHD + t], o);
        g_aohi[(size_t)(b * NT + i) * DM + h * DHD + t] = __float2half_rn(o);
    }
}

// ---------------- sym_tensor: in-place, one batch (out points at that batch's block) ----------------
__global__ void sym_kernel(float* __restrict__ out) {
    size_t i4 = (size_t)blockIdx.x * blockDim.x + threadIdx.x;
    if (i4 >= (ETOT / 2) / 4) return;
    size_t idx = i4 * 4;
    int d = (int)(idx % DM);
    size_t r = idx / DM;
    int j = (int)(r % NT);
    int i = (int)(r / NT);      // batch-local (single batch per launch)
    if (i <= j) return;
    float4 u = *(const float4*)&out[((size_t)j * NT + i) * DM + d];
    bool nx = fabsf(u.x) > 0.f, ny = fabsf(u.y) > 0.f;
    bool nz = fabsf(u.z) > 0.f, nw = fabsf(u.w) > 0.f;
    if (nx & ny & nz & nw) {
        *(float4*)&out[idx] = u;
    } else {
        if (nx) out[idx + 0] = u.x;
        if (ny) out[idx + 1] = u.y;
        if (nz) out[idx + 2] = u.z;
        if (nw) out[idx + 3] = u.w;
    }
}

// ---------------- host launch ----------------
extern "C" void kernel_launch(void* const* d_in, const int* in_sizes, int n_in,
                              void* d_out, int out_size) {
    const float* h      = (const float*)d_in[0];
    const float* e      = (const float*)d_in[1];
    const float* Wq     = (const float*)d_in[2];
    const float* Wk     = (const float*)d_in[3];
    const float* Wv     = (const float*)d_in[4];
    const float* We     = (const float*)d_in[5];
    const float* Wni    = (const float*)d_in[6];
    const float* Wnj    = (const float*)d_in[7];
    const float* Woh    = (const float*)d_in[8];
    const float* boh    = (const float*)d_in[9];
    const float* Woe    = (const float*)d_in[10];
    const float* boe    = (const float*)d_in[11];
    const float* bn1_g  = (const float*)d_in[12];
    const float* bn1_b  = (const float*)d_in[13];
    const float* bn2_g  = (const float*)d_in[14];
    const float* bn2_b  = (const float*)d_in[15];
    const float* ln1_g  = (const float*)d_in[16];
    const float* ln1_b  = (const float*)d_in[17];
    const float* ln2_g  = (const float*)d_in[18];
    const float* ln2_b  = (const float*)d_in[19];
    const float* ffh_w1 = (const float*)d_in[20];
    const float* ffh_w3 = (const float*)d_in[21];
    const float* ffh_w2 = (const float*)d_in[22];
    const float* ffe_w1 = (const float*)d_in[23];
    const float* ffe_w3 = (const float*)d_in[24];
    const float* ffe_w2 = (const float*)d_in[25];
    float* out = (float*)d_out;

    float *h1, *h2, *qkv;
    HT *e1hi, *e2hi, *evhi, *Shi, *h1hi, *aohi, *xhhi, *shhi, *whi;
    cudaGetSymbolAddress((void**)&h1, g_h1);
    cudaGetSymbolAddress((void**)&h2, g_h2);
    cudaGetSymbolAddress((void**)&qkv, g_qkv);
    cudaGetSymbolAddress((void**)&e1hi, g_e1hi);
    cudaGetSymbolAddress((void**)&e2hi, g_e2hi);
    cudaGetSymbolAddress((void**)&evhi, g_evhi);
    cudaGetSymbolAddress((void**)&Shi, g_Shi);
    cudaGetSymbolAddress((void**)&h1hi, g_h1hi);
    cudaGetSymbolAddress((void**)&aohi, g_aohi);
    cudaGetSymbolAddress((void**)&xhhi, g_xhhi);
    cudaGetSymbolAddress((void**)&shhi, g_shhi);
    cudaGetSymbolAddress((void**)&whi, g_whi);

    // weight pool offsets (transposed [N,K] fp16)
    const size_t O_We = 1310720, O_Woh = 1572864, O_Woe = 1835008;
    const size_t O_fh13 = 2097152, O_fh2 = 4194304;
    const size_t O_fe13 = 5242880, O_fe2 = 7340032;

    // streams + events (created once, outside any capture)
    static cudaStream_t s2 = nullptr, s3 = nullptr;
    static cudaEvent_t evFork, evW, evW2, evQkv, evEv0, evEv1, evB1, evJoin;
    if (!s2) {
        cudaStreamCreateWithFlags(&s2, cudaStreamNonBlocking);
        cudaStreamCreateWithFlags(&s3, cudaStreamNonBlocking);
        cudaEventCreateWithFlags(&evFork, cudaEventDisableTiming);
        cudaEventCreateWithFlags(&evW,    cudaEventDisableTiming);
        cudaEventCreateWithFlags(&evW2,   cudaEventDisableTiming);
        cudaEventCreateWithFlags(&evQkv,  cudaEventDisableTiming);
        cudaEventCreateWithFlags(&evEv0,  cudaEventDisableTiming);
        cudaEventCreateWithFlags(&evEv1,  cudaEventDisableTiming);
        cudaEventCreateWithFlags(&evB1,   cudaEventDisableTiming);
        cudaEventCreateWithFlags(&evJoin, cudaEventDisableTiming);
    }

    dim3 tb(32, 8);
    WPtr8 w8; w8.p[0] = Wq; w8.p[1] = Wk; w8.p[2] = Wv; w8.p[3] = Wni;
    w8.p[4] = Wnj; w8.p[5] = We; w8.p[6] = Woh; w8.p[7] = Woe;
    WPtr4 w4; w4.p[0] = ffh_w1; w4.p[1] = ffh_w3; w4.p[2] = ffe_w1; w4.p[3] = ffe_w3;

    // batch offsets
    const size_t eOfs = (size_t)EHALF * DM;     // into e1hi/e2hi/evhi/out-e block
    const size_t sOfs = (size_t)EHALF * HIDD;   // into Shi

    // ---- fork ----
    cudaEventRecord(evFork, 0);
    cudaStreamWaitEvent(s2, evFork, 0);
    cudaStreamWaitEvent(s3, evFork, 0);

    // ---- NULL: small weights, then batch-0 LayerNorm ----
    wcvt8<<<dim3(16, 16, 8), tb>>>(w8, whi);
    cudaEventRecord(evW, 0);
    ln_cvt<<<EHALF, 128>>>(e, e1hi, ln1_g, ln1_b);

    // ---- s3: batch-1 LayerNorm ----
    ln_cvt<<<EHALF, 128, 0, s3>>>(e + eOfs, e1hi + eOfs, ln1_g, ln1_b);

    // ---- s2: node normalization + qkv + FFN weights ----
    bn_part<<<64, 256, 0, s2>>>(h);
    bn_fin<<<16, 256, 0, s2>>>(bn1_g, bn1_b);
    bn_apply_cvt<<<HTOT / 4 / 256, 256, 0, s2>>>(h, h1, h1hi);
    cudaStreamWaitEvent(s2, evW, 0);
    tc_gemm<0><<<dim3(20, 2), 256, 0, s2>>>(h1hi, whi, qkv, 256, QKVW, 512,
                                            nullptr, nullptr, nullptr, nullptr, nullptr, nullptr, 0);
    cudaEventRecord(evQkv, s2);
    wcvt13<<<dim3(64, 16, 4), tb, 0, s2>>>(w4, whi + O_fh13, whi + O_fe13);
    wcvt2<<<dim3(16, 64, 2), tb, 0, s2>>>(ffh_w2, ffe_w2, whi + O_fh2, whi + O_fe2);
    cudaEventRecord(evW2, s2);

    // ---- NULL: batch-0 edge chain ----
    cudaStreamWaitEvent(0, evQkv, 0);
    tc_gemm<1><<<dim3(4, 128), 256>>>(e1hi, whi + O_We, nullptr, EHALF, 512, 512,
                                      nullptr, nullptr, nullptr, evhi,
                                      qkv + 3 * DM, qkv + 4 * DM, QKVW);
    cudaEventRecord(evEv0, 0);
    tc_gemm<3><<<dim3(4, 128), 256>>>(evhi, whi + O_Woe, nullptr, EHALF, 512, 512,
                                      boe, nullptr, e1hi, e2hi, nullptr, nullptr, 0);
    ln_cvt_h<<<EHALF, 128>>>(e2hi, e1hi, ln2_g, ln2_b);
    cudaStreamWaitEvent(0, evW2, 0);
    tc_gemm<2><<<dim3(32, 128), 256>>>(e1hi, whi + O_fe13, nullptr, EHALF, 4096, 512,
                                       nullptr, nullptr, nullptr, Shi, nullptr, nullptr, 0);
    tc_gemm<0><<<dim3(4, 128), 256>>>(Shi, whi + O_fe2, out + HTOT, EHALF, 512, 2048,
                                      nullptr, nullptr, e2hi, nullptr, nullptr, nullptr, 0);
    sym_kernel<<<(int)((ETOT / 2 / 4) / 256), 256>>>(out + HTOT);

    // ---- s3: batch-1 edge chain (independent, co-scheduled) ----
    cudaStreamWaitEvent(s3, evQkv, 0);
    tc_gemm<1><<<dim3(4, 128), 256, 0, s3>>>(e1hi + eOfs, whi + O_We, nullptr, EHALF, 512, 512,
                                             nullptr, nullptr, nullptr, evhi + eOfs,
                                             qkv + (size_t)NT * QKVW + 3 * DM,
                                             qkv + (size_t)NT * QKVW + 4 * DM, QKVW);
    cudaEventRecord(evEv1, s3);
    tc_gemm<3><<<dim3(4, 128), 256, 0, s3>>>(evhi + eOfs, whi + O_Woe, nullptr, EHALF, 512, 512,
                                             boe, nullptr, e1hi + eOfs, e2hi + eOfs, nullptr, nullptr, 0);
    ln_cvt_h<<<EHALF, 128, 0, s3>>>(e2hi + eOfs, e1hi + eOfs, ln2_g, ln2_b);
    cudaStreamWaitEvent(s3, evW2, 0);
    tc_gemm<2><<<dim3(32, 128), 256, 0, s3>>>(e1hi + eOfs, whi + O_fe13, nullptr, EHALF, 4096, 512,
                                              nullptr, nullptr, nullptr, Shi + sOfs, nullptr, nullptr, 0);
    tc_gemm<0><<<dim3(4, 128), 256, 0, s3>>>(Shi + sOfs, whi + O_fe2, out + HTOT + eOfs, EHALF, 512, 2048,
                                             nullptr, nullptr, e2hi + eOfs, nullptr, nullptr, nullptr, 0);
    sym_kernel<<<(int)((ETOT / 2 / 4) / 256), 256, 0, s3>>>(out + HTOT + eOfs);
    cudaEventRecord(evB1, s3);

    // ---- s2: attention + node output + node FFN (overlaps edge GEMMs) ----
    cudaStreamWaitEvent(s2, evEv0, 0);
    cudaStreamWaitEvent(s2, evEv1, 0);
    attn_kernel<<<BSZ * NH * NT, 128, 0, s2>>>();
    tc_gemm<0><<<dim3(4, 2), 256, 0, s2>>>(aohi, whi + O_Woh, h2, 256, 512, 512,
                                           boh, h1, nullptr, nullptr, nullptr, nullptr, 0);
    bn_part<<<64, 256, 0, s2>>>(h2);
    bn_fin<<<16, 256, 0, s2>>>(bn2_g, bn2_b);
    bn_apply_cvt<<<HTOT / 4 / 256, 256, 0, s2>>>(h2, nullptr, xhhi);
    tc_gemm<2><<<dim3(32, 2), 256, 0, s2>>>(xhhi, whi + O_fh13, nullptr, 256, 4096, 512,
                                            nullptr, nullptr, nullptr, shhi, nullptr, nullptr, 0);
    tc_gemm<0><<<dim3(4, 2), 256, 0, s2>>>(shhi, whi + O_fh2, out, 256, 512, 2048,
                                           nullptr, h2, nullptr, nullptr, nullptr, nullptr, 0);
    cudaEventRecord(evJoin, s2);

    // ---- join ----
    cudaStreamWaitEvent(0, evJoin, 0);
    cudaStreamWaitEvent(0, evB1, 0);
}

// round 16
// speedup vs baseline: 1.5432x; 1.5432x over previous
#include <cuda_runtime.h>
#include <cuda_fp16.h>
#include <math.h>
#include <stdint.h>

// Problem constants
#define BSZ 2
#define NT  128
#define DM  512
#define NH  8
#define DHD 64
#define HIDD 2048
#define EPSC 1e-5f

#define HTOT (BSZ*NT*DM)                 // 131072
#define EROWS (BSZ*NT*NT)                // 32768
#define EHALF (EROWS/2)                  // 16384
#define ETOT ((size_t)EROWS*DM)          // 16777216
#define QKVW 2560
#define WPOOL 8388608

// compacted upper-triangle rows per batch: 128*129/2 = 8256, padded to 65 tiles
#define CROWS 8256
#define CPAD  8320
#define CTILES 65

typedef __half HT;

// ---------------- scratch (static device allocations) ----------------
__device__ float g_h1[HTOT];
__device__ float g_h2[HTOT];
__device__ float g_qkv[BSZ*NT*QKVW];
__device__ float g_scale[DM], g_shift[DM];
__device__ float g_pS[64][DM], g_pQ[64][DM];
__device__ int   g_rmap[2*CPAD];

__device__ HT g_e1hi[(size_t)EROWS*DM];
__device__ HT g_e2c[(size_t)2*CPAD*DM];
__device__ HT g_evhi[(size_t)EROWS*DM];
__device__ HT g_Shi[(size_t)2*CPAD*HIDD];
__device__ HT g_h1hi[HTOT];
__device__ HT g_aohi[HTOT];
__device__ HT g_xhhi[HTOT];
__device__ HT g_shhi[BSZ*NT*HIDD];
__device__ HT g_whi[WPOOL];

// ---------------- helpers ----------------
__device__ __forceinline__ uint32_t smem_u32(const void* p) {
    uint32_t a;
    asm("{ .reg .u64 t; cvta.to.shared.u64 t, %1; cvt.u32.u64 %0, t; }" : "=r"(a) : "l"(p));
    return a;
}
__device__ __forceinline__ void ldsm_x4(uint32_t* r, uint32_t addr) {
    asm volatile("ldmatrix.sync.aligned.m8n8.x4.shared.b16 {%0,%1,%2,%3}, [%4];"
                 : "=r"(r[0]), "=r"(r[1]), "=r"(r[2]), "=r"(r[3]) : "r"(addr));
}
__device__ __forceinline__ void mma_fp16(float* d, const uint32_t* a, uint32_t b0, uint32_t b1) {
    asm volatile(
        "mma.sync.aligned.m16n8k16.row.col.f32.f16.f16.f32 "
        "{%0,%1,%2,%3}, {%4,%5,%6,%7}, {%8,%9}, {%0,%1,%2,%3};"
        : "+f"(d[0]), "+f"(d[1]), "+f"(d[2]), "+f"(d[3])
        : "r"(a[0]), "r"(a[1]), "r"(a[2]), "r"(a[3]), "r"(b0), "r"(b1));
}
__device__ __forceinline__ void cvt4_hi(const float4& o, HT* hi) {
    __half2 p01 = __floats2half2_rn(o.x, o.y);
    __half2 p23 = __floats2half2_rn(o.z, o.w);
    uint2 hv;
    hv.x = *(uint32_t*)&p01;
    hv.y = *(uint32_t*)&p23;
    *(uint2*)hi = hv;
}
__device__ __forceinline__ float2 h2f2(const HT* p) {
    __half2 h = *(const __half2*)p;
    return __half22float2(h);
}

// ---------------- mma.sync GEMM: C[M,N] = sum_k A[M,K]*B[N,K]  (B is W^T) ----------------
// pure fp16 operands, fp32 accumulate, single pass.
// BM=BN=128, BK=32, 256 threads (8 warps: 4 m x 2 n), warp tile 32x64,
// LDG-prefetch double buffer, ONE __syncthreads per K-iter.
// MODE 0: C = acc (+bias)(+add fp32)(+addh fp16), fp32 out.  MAPPED: C row = rmap[row] (guarded)
// MODE 1: v = acc + aux1[(row>>7)*aS+col] + aux2[((row>>14)*128+(row&127))*aS+col] -> Ohi fp16
// MODE 2: interleaved (u,t) col pairs; silu(u)*t -> Ohi fp16 at [row, col/2] (staged)
// MODE 3: v = acc + bias + addh(fp16) -> Ohi fp16 (staged). MAPPED: A + addh rows = rmap[row]
#define PADR 40   // smem row stride in fp16 elements (80 bytes)

template<int MODE, int MAPPED>
__global__ __launch_bounds__(256, 2) void tc_gemm(
    const HT* __restrict__ Ahi, const HT* __restrict__ Bhi,
    float* __restrict__ C, int M, int N, int K,
    const float* __restrict__ bias, const float* __restrict__ add,
    const HT* __restrict__ addh,
    HT* __restrict__ Ohi,
    const float* __restrict__ aux1, const float* __restrict__ aux2, int aS,
    const int* __restrict__ rmap)
{
    __shared__ __align__(16) HT sA[2][128 * PADR];
    __shared__ __align__(16) HT sB[2][128 * PADR];

    const int tid = threadIdx.x, lane = tid & 31, wid = tid >> 5;
    const int warp_m = wid & 3, warp_n = wid >> 2;
    const int m0 = blockIdx.y * 128, n0 = blockIdx.x * 128;
    const int total = K >> 5;

    const int lr = tid >> 2;     // 0..63
    const int lg = tid & 3;      // k-group of 8

    // A-row indices (possibly gathered through the row map, MODE3)
    int mr0 = m0 + lr, mr1 = m0 + lr + 64;
    if (MAPPED && MODE == 3) {
        int t0 = rmap[mr0]; mr0 = t0 < 0 ? 0 : t0;
        int t1 = rmap[mr1]; mr1 = t1 < 0 ? 0 : t1;
    }

    float acc[2][8][4];
    #pragma unroll
    for (int s = 0; s < 2; s++)
        #pragma unroll
        for (int f = 0; f < 8; f++)
            #pragma unroll
            for (int u = 0; u < 4; u++) acc[s][f][u] = 0.f;

    uint4 pa[2], pb[2];
    auto LOADREGS = [&](int it) {
        pa[0] = *(const uint4*)(Ahi + (size_t)mr0 * K + it * 32 + lg * 8);
        pa[1] = *(const uint4*)(Ahi + (size_t)mr1 * K + it * 32 + lg * 8);
        const HT* bb = Bhi + (size_t)(n0 + lr) * K + it * 32 + lg * 8;
        pb[0] = *(const uint4*)bb;
        pb[1] = *(const uint4*)(bb + (size_t)64 * K);
    };
    auto STORESM = [&](int buf) {
        *(uint4*)&sA[buf][lr * PADR + lg * 8] = pa[0];
        *(uint4*)&sA[buf][(lr + 64) * PADR + lg * 8] = pa[1];
        *(uint4*)&sB[buf][lr * PADR + lg * 8] = pb[0];
        *(uint4*)&sB[buf][(lr + 64) * PADR + lg * 8] = pb[1];
    };

    const uint32_t aBase = smem_u32(&sA[0][0]);
    const uint32_t bBase = smem_u32(&sB[0][0]);
    const uint32_t BUFB = 128 * PADR * 2;
    const uint32_t aoff = ((warp_m * 32 + (lane & 15)) * PADR + (lane >> 4) * 8) * 2;
    const uint32_t boff = ((warp_n * 64 + (lane & 15)) * PADR + (lane >> 4) * 8) * 2;

    LOADREGS(0);
    STORESM(0);
    __syncthreads();

    for (int it = 0; it < total; ++it) {
        const int buf = it & 1;
        if (it + 1 < total) LOADREGS(it + 1);

        const uint32_t ab = aBase + buf * BUFB + aoff;
        const uint32_t bb = bBase + buf * BUFB + boff;
        #pragma unroll
        for (int kk = 0; kk < 32; kk += 16) {
            uint32_t A0[4], A1[4], Bf[4][4];
            ldsm_x4(A0, ab + kk * 2);
            ldsm_x4(A1, ab + kk * 2 + 16 * PADR * 2);
            #pragma unroll
            for (int g = 0; g < 4; g++) ldsm_x4(Bf[g], bb + kk * 2 + g * 16 * PADR * 2);
            #pragma unroll
            for (int fn = 0; fn < 8; fn++) {
                uint32_t b0 = Bf[fn >> 1][fn & 1];
                uint32_t b1 = Bf[fn >> 1][(fn & 1) + 2];
                mma_fp16(acc[0][fn], A0, b0, b1);
                mma_fp16(acc[1][fn], A1, b0, b1);
            }
        }
        if (it + 1 < total) STORESM(buf ^ 1);
        __syncthreads();
    }

    if (MODE == 0) {
        #pragma unroll
        for (int s = 0; s < 2; s++) {
            int ra = m0 + warp_m * 32 + s * 16 + (lane >> 2);
            int rb = ra + 8;
            int cra = MAPPED ? rmap[ra] : ra;
            int crb = MAPPED ? rmap[rb] : rb;
            #pragma unroll
            for (int fn = 0; fn < 8; fn++) {
                int cb = n0 + warp_n * 64 + fn * 8 + (lane & 3) * 2;
                float2 v0 = {acc[s][fn][0], acc[s][fn][1]};
                float2 v1 = {acc[s][fn][2], acc[s][fn][3]};
                if (bias) {
                    float2 bv = *(const float2*)(bias + cb);
                    v0.x += bv.x; v0.y += bv.y;
                    v1.x += bv.x; v1.y += bv.y;
                }
                if (add) {
                    float2 a0 = *(const float2*)(add + (size_t)ra * N + cb);
                    float2 a1 = *(const float2*)(add + (size_t)rb * N + cb);
                    v0.x += a0.x; v0.y += a0.y;
                    v1.x += a1.x; v1.y += a1.y;
                }
                if (addh) {
                    float2 a0 = h2f2(addh + (size_t)ra * N + cb);
                    float2 a1 = h2f2(addh + (size_t)rb * N + cb);
                    v0.x += a0.x; v0.y += a0.y;
                    v1.x += a1.x; v1.y += a1.y;
                }
                if (!MAPPED || cra >= 0) *(float2*)(C + (size_t)cra * N + cb) = v0;
                if (!MAPPED || crb >= 0) *(float2*)(C + (size_t)crb * N + cb) = v1;
            }
        }
    } else if (MODE == 1 || MODE == 3) {
        // stage fp16 (16 rows x 64 cols per warp, row stride 72)
        HT* stg = &sA[0][0] + wid * (16 * 72);
        #pragma unroll
        for (int s = 0; s < 2; s++) {
            int ra = m0 + warp_m * 32 + s * 16 + (lane >> 2);
            int rb = ra + 8;
            int era = ra, erb = rb;
            if (MAPPED && MODE == 3) {
                int t0 = rmap[ra]; era = t0 < 0 ? 0 : t0;
                int t1 = rmap[rb]; erb = t1 < 0 ? 0 : t1;
            }
            const float* a1rA = (MODE == 1) ? aux1 + (size_t)(ra >> 7) * aS : nullptr;
            const float* a2rA = (MODE == 1) ? aux2 + ((size_t)(ra >> 14) * 128 + (ra & 127)) * aS : nullptr;
            const float* a2rB = (MODE == 1) ? aux2 + ((size_t)(rb >> 14) * 128 + (rb & 127)) * aS : nullptr;
            #pragma unroll
            for (int fn = 0; fn < 8; fn++) {
                int cb = n0 + warp_n * 64 + fn * 8 + (lane & 3) * 2;
                float2 v0 = {acc[s][fn][0], acc[s][fn][1]};
                float2 v1 = {acc[s][fn][2], acc[s][fn][3]};
                if (MODE == 1) {
                    float2 x1 = *(const float2*)(a1rA + cb);
                    float2 xa = *(const float2*)(a2rA + cb);
                    float2 xb = *(const float2*)(a2rB + cb);
                    v0.x += x1.x + xa.x; v0.y += x1.y + xa.y;
                    v1.x += x1.x + xb.x; v1.y += x1.y + xb.y;
                } else {
                    if (bias) {
                        float2 bv = *(const float2*)(bias + cb);
                        v0.x += bv.x; v0.y += bv.y;
                        v1.x += bv.x; v1.y += bv.y;
                    }
                    float2 a0 = h2f2(addh + (size_t)era * N + cb);
                    float2 a1 = h2f2(addh + (size_t)erb * N + cb);
                    v0.x += a0.x; v0.y += a0.y;
                    v1.x += a1.x; v1.y += a1.y;
                }
                int c0 = fn * 8 + (lane & 3) * 2;
                __half2 h0 = __floats2half2_rn(v0.x, v0.y);
                __half2 h1 = __floats2half2_rn(v1.x, v1.y);
                *(__half2*)&stg[(lane >> 2) * 72 + c0] = h0;
                *(__half2*)&stg[((lane >> 2) + 8) * 72 + c0] = h1;
            }
            __syncwarp();
            {
                int row = lane >> 1, half = lane & 1;
                const uint4* src = (const uint4*)&stg[row * 72 + half * 32];
                int grow = m0 + warp_m * 32 + s * 16 + row;
                uint4* dst = (uint4*)(Ohi + (size_t)grow * N + n0 + warp_n * 64 + half * 32);
                dst[0] = src[0]; dst[1] = src[1]; dst[2] = src[2]; dst[3] = src[3];
            }
            __syncwarp();
        }
    } else {  // MODE 2
        HT* stg = &sA[0][0] + wid * (16 * 40);
        const int NS = N >> 1;
        #pragma unroll
        for (int s = 0; s < 2; s++) {
            #pragma unroll
            for (int fn = 0; fn < 8; fn++) {
                float u0 = acc[s][fn][0], t0 = acc[s][fn][1];
                float u1 = acc[s][fn][2], t1 = acc[s][fn][3];
                float s0 = u0 / (1.f + expf(-u0)) * t0;
                float s1 = u1 / (1.f + expf(-u1)) * t1;
                int c = fn * 4 + (lane & 3);
                stg[(lane >> 2) * 40 + c] = __float2half_rn(s0);
                stg[((lane >> 2) + 8) * 40 + c] = __float2half_rn(s1);
            }
            __syncwarp();
            {
                int row = lane >> 1, half = lane & 1;
                const uint4* src = (const uint4*)&stg[row * 40 + half * 16];
                int grow = m0 + warp_m * 32 + s * 16 + row;
                uint4* dst = (uint4*)(Ohi + (size_t)grow * NS + (n0 >> 1) + warp_n * 32 + half * 16);
                dst[0] = src[0]; dst[1] = src[1];
            }
            __syncwarp();
        }
    }
}

// ---------------- row map: compacted upper-triangle rows -> global orig rows ----------------
__global__ void build_map() {
    int idx = blockIdx.x * 256 + threadIdx.x;
    if (idx >= 2 * CPAD) return;
    int b = idx / CPAD, rc = idx % CPAD;
    int val = -1;
    if (rc < CROWS) {
        int i = 0, base = 0;
        while (base + (NT - i) <= rc) { base += NT - i; i++; }
        int j = i + (rc - base);
        val = b * EHALF + i * NT + j;
    }
    g_rmap[idx] = val;
}

// ---------------- batched weight transpose: w[K,N] fp32 -> hi fp16 ----------------
struct WPtr8 { const float* p[8]; };

__global__ void wcvt8(WPtr8 wb, HT* __restrict__ hi) {
    __shared__ float t[32][33];
    int z = blockIdx.z;
    const float* w = wb.p[z];
    HT* dst = hi + (size_t)z * 262144;
    int kb = blockIdx.y * 32, nb = blockIdx.x * 32;
    int tx = threadIdx.x, ty = threadIdx.y;  // 32x8
    #pragma unroll
    for (int i = 0; i < 32; i += 8)
        t[ty + i][tx] = w[(size_t)(kb + ty + i) * 512 + nb + tx];
    __syncthreads();
    #pragma unroll
    for (int i = 0; i < 32; i += 8)
        dst[(size_t)(nb + ty + i) * 512 + kb + tx] = __float2half_rn(t[tx][ty + i]);
}

struct WPtr4 { const float* p[4]; };
__global__ void wcvt13(WPtr4 wb, HT* __restrict__ hiA, HT* __restrict__ hiB) {
    __shared__ float t[32][33];
    int z = blockIdx.z;
    const float* w = wb.p[z];
    HT* dst = (z < 2) ? hiA : hiB;
    int ofs = z & 1;
    int kb = blockIdx.y * 32, nb = blockIdx.x * 32;
    int tx = threadIdx.x, ty = threadIdx.y;
    #pragma unroll
    for (int i = 0; i < 32; i += 8)
        t[ty + i][tx] = w[(size_t)(kb + ty + i) * 2048 + nb + tx];
    __syncthreads();
    #pragma unroll
    for (int i = 0; i < 32; i += 8)
        dst[((size_t)(nb + ty + i) * 2 + ofs) * 512 + kb + tx] = __float2half_rn(t[tx][ty + i]);
}

__global__ void wcvt2(const float* __restrict__ wa, const float* __restrict__ wb,
                      HT* __restrict__ hiA, HT* __restrict__ hiB) {
    __shared__ float t[32][33];
    int z = blockIdx.z;
    const float* w = z ? wb : wa;
    HT* dst = z ? hiB : hiA;
    int kb = blockIdx.y * 32, nb = blockIdx.x * 32;
    int tx = threadIdx.x, ty = threadIdx.y;
    #pragma unroll
    for (int i = 0; i < 32; i += 8)
        t[ty + i][tx] = w[(size_t)(kb + ty + i) * 512 + nb + tx];
    __syncthreads();
    #pragma unroll
    for (int i = 0; i < 32; i += 8)
        dst[(size_t)(nb + ty + i) * 2048 + kb + tx] = __float2half_rn(t[tx][ty + i]);
}

// ---------------- BatchNorm: two-phase parallel stats ----------------
__global__ void bn_part(const float* __restrict__ x) {
    int blk = blockIdx.x;
    int t = threadIdx.x;
    int c = t * 2;
    float s0 = 0.f, s1 = 0.f, q0 = 0.f, q1 = 0.f;
    #pragma unroll
    for (int r = 0; r < 4; r++) {
        float2 v = *(const float2*)(x + (size_t)(blk * 4 + r) * DM + c);
        s0 += v.x; s1 += v.y;
        q0 = fmaf(v.x, v.x, q0); q1 = fmaf(v.y, v.y, q1);
    }
    g_pS[blk][c] = s0; g_pS[blk][c + 1] = s1;
    g_pQ[blk][c] = q0; g_pQ[blk][c + 1] = q1;
}

__global__ void bn_fin(const float* __restrict__ g, const float* __restrict__ b) {
    int tid = threadIdx.x;
    int c = blockIdx.x * 32 + (tid >> 3);
    int slot = tid & 7;
    float s = 0.f, q = 0.f;
    #pragma unroll
    for (int t = 0; t < 8; t++) { s += g_pS[slot + 8 * t][c]; q += g_pQ[slot + 8 * t][c]; }
    #pragma unroll
    for (int o = 4; o; o >>= 1) {
        s += __shfl_xor_sync(0xffffffffu, s, o);
        q += __shfl_xor_sync(0xffffffffu, q, o);
    }
    if (slot == 0) {
        const float inv = 1.f / (BSZ * NT);
        float m = s * inv;
        float var = q * inv - m * m;
        float sc = g[c] / sqrtf(var + EPSC);
        g_scale[c] = sc;
        g_shift[c] = b[c] - m * sc;
    }
}

__global__ void bn_apply_cvt(const float* __restrict__ x, float* __restrict__ y,
                             HT* __restrict__ hi) {
    int i = blockIdx.x * blockDim.x + threadIdx.x;
    if (i >= HTOT / 4) return;
    int idx = i * 4;
    int c = idx & (DM - 1);
    float4 v = *(const float4*)(x + idx);
    float4 o;
    o.x = fmaf(v.x, g_scale[c + 0], g_shift[c + 0]);
    o.y = fmaf(v.y, g_scale[c + 1], g_shift[c + 1]);
    o.z = fmaf(v.z, g_scale[c + 2], g_shift[c + 2]);
    o.w = fmaf(v.w, g_scale[c + 3], g_shift[c + 3]);
    if (y) *(float4*)(y + idx) = o;
    cvt4_hi(o, hi + idx);
}

// ---------------- LayerNorm, fp32 in -> fp16 hi ----------------
__global__ void ln_cvt(const float* __restrict__ x, HT* __restrict__ hi,
                       const float* __restrict__ g, const float* __restrict__ b) {
    int row = blockIdx.x;
    int t = threadIdx.x;
    float4 v = ((const float4*)(x + (size_t)row * DM))[t];
    float s  = v.x + v.y + v.z + v.w;
    float s2 = fmaf(v.x, v.x, fmaf(v.y, v.y, fmaf(v.z, v.z, v.w * v.w)));
    #pragma unroll
    for (int o = 16; o; o >>= 1) {
        s  += __shfl_xor_sync(0xffffffffu, s,  o);
        s2 += __shfl_xor_sync(0xffffffffu, s2, o);
    }
    __shared__ float sa[4], sbx[4];
    if ((t & 31) == 0) { sa[t >> 5] = s; sbx[t >> 5] = s2; }
    __syncthreads();
    s  = sa[0] + sa[1] + sa[2] + sa[3];
    s2 = sbx[0] + sbx[1] + sbx[2] + sbx[3];
    const float inv = 1.f / DM;
    float m  = s * inv;
    float var = s2 * inv - m * m;
    float rs = rsqrtf(var + EPSC);
    float4 gg = ((const float4*)g)[t];
    float4 bb = ((const float4*)b)[t];
    float4 o;
    o.x = fmaf((v.x - m) * rs, gg.x, bb.x);
    o.y = fmaf((v.y - m) * rs, gg.y, bb.y);
    o.z = fmaf((v.z - m) * rs, gg.z, bb.z);
    o.w = fmaf((v.w - m) * rs, gg.w, bb.w);
    cvt4_hi(o, hi + (size_t)row * DM + t * 4);
}

// ---------------- LayerNorm, fp16 in -> fp16 hi ----------------
__global__ void ln_cvt_h(const HT* __restrict__ x, HT* __restrict__ hi,
                         const float* __restrict__ g, const float* __restrict__ b) {
    int row = blockIdx.x;
    int t = threadIdx.x;
    uint2 raw = ((const uint2*)(x + (size_t)row * DM))[t];
    float2 f01 = __half22float2(*(__half2*)&raw.x);
    float2 f23 = __half22float2(*(__half2*)&raw.y);
    float4 v = {f01.x, f01.y, f23.x, f23.y};
    float s  = v.x + v.y + v.z + v.w;
    float s2 = fmaf(v.x, v.x, fmaf(v.y, v.y, fmaf(v.z, v.z, v.w * v.w)));
    #pragma unroll
    for (int o = 16; o; o >>= 1) {
        s  += __shfl_xor_sync(0xffffffffu, s,  o);
        s2 += __shfl_xor_sync(0xffffffffu, s2, o);
    }
    __shared__ float sa[4], sbx[4];
    if ((t & 31) == 0) { sa[t >> 5] = s; sbx[t >> 5] = s2; }
    __syncthreads();
    s  = sa[0] + sa[1] + sa[2] + sa[3];
    s2 = sbx[0] + sbx[1] + sbx[2] + sbx[3];
    const float inv = 1.f / DM;
    float m  = s * inv;
    float var = s2 * inv - m * m;
    float rs = rsqrtf(var + EPSC);
    float4 gg = ((const float4*)g)[t];
    float4 bb = ((const float4*)b)[t];
    float4 o;
    o.x = fmaf((v.x - m) * rs, gg.x, bb.x);
    o.y = fmaf((v.y - m) * rs, gg.y, bb.y);
    o.z = fmaf((v.z - m) * rs, gg.z, bb.z);
    o.w = fmaf((v.w - m) * rs, gg.w, bb.w);
    cvt4_hi(o, hi + (size_t)row * DM + t * 4);
}

// ---------------- attention: one block per (b,h,i), 128 threads, fp16 out ----------------
__global__ void attn_kernel() {
    int i = blockIdx.x % NT;
    int h = (blockIdx.x / NT) % NH;
    int b = blockIdx.x / (NT * NH);
    int t = threadIdx.x;
    __shared__ float qs[DHD];
    __shared__ float scs[NT];
    __shared__ float red[4];

    if (t < DHD) qs[t] = g_qkv[(size_t)(b * NT + i) * QKVW + h * DHD + t];
    __syncthreads();

    const HT* evrow = g_evhi + ((size_t)(b * NT + i) * NT + t) * DM + h * DHD;
    const float* krow = g_qkv + (size_t)(b * NT + t) * QKVW + DM + h * DHD;
    float s = 0.f;
    #pragma unroll 8
    for (int d = 0; d < DHD; d++)
        s = fmaf(qs[d] * __half2float(evrow[d]), krow[d], s);
    s *= 0.125f;

    float m = s;
    #pragma unroll
    for (int o = 16; o; o >>= 1) m = fmaxf(m, __shfl_xor_sync(0xffffffffu, m, o));
    if ((t & 31) == 0) red[t >> 5] = m;
    __syncthreads();
    m = fmaxf(fmaxf(red[0], red[1]), fmaxf(red[2], red[3]));
    float p = expf(s - m);
    float ssum = p;
    #pragma unroll
    for (int o = 16; o; o >>= 1) ssum += __shfl_xor_sync(0xffffffffu, ssum, o);
    __syncthreads();
    if ((t & 31) == 0) red[t >> 5] = ssum;
    __syncthreads();
    ssum = red[0] + red[1] + red[2] + red[3];
    scs[t] = p / ssum;
    __syncthreads();

    if (t < DHD) {
        float o = 0.f;
        #pragma unroll 8
        for (int j = 0; j < NT; j++)
            o = fmaf(scs[j], g_qkv[(size_t)(b * NT + j) * QKVW + 2 * DM + h * DHD + t], o);
        g_aohi[(size_t)(b * NT + i) * DM + h * DHD + t] = __float2half_rn(o);
    }
}

// ---------------- sym_expand: lower[i,j] = upper[j,i] (one batch, in place) ----------------
__global__ void sym_expand(float* __restrict__ out) {
    size_t i4 = (size_t)blockIdx.x * blockDim.x + threadIdx.x;
    if (i4 >= (ETOT / 2) / 4) return;
    size_t idx = i4 * 4;
    int d = (int)(idx % DM);
    size_t r = idx / DM;
    int j = (int)(r % NT);
    int i = (int)(r / NT);
    if (i <= j) return;
    float4 u = *(const float4*)&out[((size_t)j * NT + i) * DM + d];
    *(float4*)&out[idx] = u;
}

// ---------------- host launch ----------------
extern "C" void kernel_launch(void* const* d_in, const int* in_sizes, int n_in,
                              void* d_out, int out_size) {
    const float* h      = (const float*)d_in[0];
    const float* e      = (const float*)d_in[1];
    const float* Wq     = (const float*)d_in[2];
    const float* Wk     = (const float*)d_in[3];
    const float* Wv     = (const float*)d_in[4];
    const float* We     = (const float*)d_in[5];
    const float* Wni    = (const float*)d_in[6];
    const float* Wnj    = (const float*)d_in[7];
    const float* Woh    = (const float*)d_in[8];
    const float* boh    = (const float*)d_in[9];
    const float* Woe    = (const float*)d_in[10];
    const float* boe    = (const float*)d_in[11];
    const float* bn1_g  = (const float*)d_in[12];
    const float* bn1_b  = (const float*)d_in[13];
    const float* bn2_g  = (const float*)d_in[14];
    const float* bn2_b  = (const float*)d_in[15];
    const float* ln1_g  = (const float*)d_in[16];
    const float* ln1_b  = (const float*)d_in[17];
    const float* ln2_g  = (const float*)d_in[18];
    const float* ln2_b  = (const float*)d_in[19];
    const float* ffh_w1 = (const float*)d_in[20];
    const float* ffh_w3 = (const float*)d_in[21];
    const float* ffh_w2 = (const float*)d_in[22];
    const float* ffe_w1 = (const float*)d_in[23];
    const float* ffe_w3 = (const float*)d_in[24];
    const float* ffe_w2 = (const float*)d_in[25];
    float* out = (float*)d_out;

    float *h1, *h2, *qkv;
    int* rmap;
    HT *e1hi, *e2c, *evhi, *Shi, *h1hi, *aohi, *xhhi, *shhi, *whi;
    cudaGetSymbolAddress((void**)&h1, g_h1);
    cudaGetSymbolAddress((void**)&h2, g_h2);
    cudaGetSymbolAddress((void**)&qkv, g_qkv);
    cudaGetSymbolAddress((void**)&rmap, g_rmap);
    cudaGetSymbolAddress((void**)&e1hi, g_e1hi);
    cudaGetSymbolAddress((void**)&e2c, g_e2c);
    cudaGetSymbolAddress((void**)&evhi, g_evhi);
    cudaGetSymbolAddress((void**)&Shi, g_Shi);
    cudaGetSymbolAddress((void**)&h1hi, g_h1hi);
    cudaGetSymbolAddress((void**)&aohi, g_aohi);
    cudaGetSymbolAddress((void**)&xhhi, g_xhhi);
    cudaGetSymbolAddress((void**)&shhi, g_shhi);
    cudaGetSymbolAddress((void**)&whi, g_whi);

    // weight pool offsets (transposed [N,K] fp16)
    const size_t O_We = 1310720, O_Woh = 1572864, O_Woe = 1835008;
    const size_t O_fh13 = 2097152, O_fh2 = 4194304;
    const size_t O_fe13 = 5242880, O_fe2 = 7340032;

    // streams + events (created once, outside any capture)
    static cudaStream_t s2 = nullptr, s3 = nullptr;
    static cudaEvent_t evFork, evW, evW2, evQkv, evEv, evLn, evE2, evB1, evJoin;
    if (!s2) {
        cudaStreamCreateWithFlags(&s2, cudaStreamNonBlocking);
        cudaStreamCreateWithFlags(&s3, cudaStreamNonBlocking);
        cudaEventCreateWithFlags(&evFork, cudaEventDisableTiming);
        cudaEventCreateWithFlags(&evW,    cudaEventDisableTiming);
        cudaEventCreateWithFlags(&evW2,   cudaEventDisableTiming);
        cudaEventCreateWithFlags(&evQkv,  cudaEventDisableTiming);
        cudaEventCreateWithFlags(&evEv,   cudaEventDisableTiming);
        cudaEventCreateWithFlags(&evLn,   cudaEventDisableTiming);
        cudaEventCreateWithFlags(&evE2,   cudaEventDisableTiming);
        cudaEventCreateWithFlags(&evB1,   cudaEventDisableTiming);
        cudaEventCreateWithFlags(&evJoin, cudaEventDisableTiming);
    }

    dim3 tb(32, 8);
    WPtr8 w8; w8.p[0] = Wq; w8.p[1] = Wk; w8.p[2] = Wv; w8.p[3] = Wni;
    w8.p[4] = Wnj; w8.p[5] = We; w8.p[6] = Woh; w8.p[7] = Woe;
    WPtr4 w4; w4.p[0] = ffh_w1; w4.p[1] = ffh_w3; w4.p[2] = ffe_w1; w4.p[3] = ffe_w3;

    // compacted batch offsets
    const size_t cOfs = (size_t)CPAD * DM;      // e2c / e1c batch stride
    const size_t sOfs = (size_t)CPAD * HIDD;    // Shi batch stride
    const size_t eOut = (size_t)EHALF * DM;     // out e-block batch stride

    // ---- fork ----
    cudaEventRecord(evFork, 0);
    cudaStreamWaitEvent(s2, evFork, 0);
    cudaStreamWaitEvent(s3, evFork, 0);

    // ---- s3: edge LayerNorm (full) ----
    ln_cvt<<<EROWS, 128, 0, s3>>>(e, e1hi, ln1_g, ln1_b);
    cudaEventRecord(evLn, s3);

    // ---- NULL: small weights + row map ----
    wcvt8<<<dim3(16, 16, 8), tb>>>(w8, whi);
    build_map<<<(2 * CPAD + 255) / 256, 256>>>();
    cudaEventRecord(evW, 0);

    // ---- s2: node normalization + qkv + FFN weights ----
    bn_part<<<64, 256, 0, s2>>>(h);
    bn_fin<<<16, 256, 0, s2>>>(bn1_g, bn1_b);
    bn_apply_cvt<<<HTOT / 4 / 256, 256, 0, s2>>>(h, h1, h1hi);
    cudaStreamWaitEvent(s2, evW, 0);
    tc_gemm<0, 0><<<dim3(20, 2), 256, 0, s2>>>(h1hi, whi, qkv, 256, QKVW, 512,
                                               nullptr, nullptr, nullptr, nullptr, nullptr, nullptr, 0, nullptr);
    cudaEventRecord(evQkv, s2);
    wcvt13<<<dim3(64, 16, 4), tb, 0, s2>>>(w4, whi + O_fh13, whi + O_fe13);
    wcvt2<<<dim3(16, 64, 2), tb, 0, s2>>>(ffh_w2, ffe_w2, whi + O_fh2, whi + O_fe2);
    cudaEventRecord(evW2, s2);

    // ---- NULL: edge projection with fused ev = eW + ni + nj (FULL rows, feeds attention) ----
    cudaStreamWaitEvent(0, evLn, 0);
    cudaStreamWaitEvent(0, evQkv, 0);
    tc_gemm<1, 0><<<dim3(4, 256), 256>>>(e1hi, whi + O_We, nullptr, EROWS, 512, 512,
                                         nullptr, nullptr, nullptr, evhi,
                                         qkv + 3 * DM, qkv + 4 * DM, QKVW, nullptr);
    cudaEventRecord(evEv, 0);

    // ---- NULL: Woe on upper-triangle rows only (mapped gather), both batches ----
    tc_gemm<3, 1><<<dim3(4, 2 * CTILES), 256>>>(evhi, whi + O_Woe, nullptr, 2 * CPAD, 512, 512,
                                                boe, nullptr, e1hi, e2c, nullptr, nullptr, 0, rmap);
    cudaEventRecord(evE2, 0);

    // ---- s2: attention + node output + node FFN (overlaps edge GEMMs) ----
    cudaStreamWaitEvent(s2, evEv, 0);
    attn_kernel<<<BSZ * NH * NT, 128, 0, s2>>>();
    tc_gemm<0, 0><<<dim3(4, 2), 256, 0, s2>>>(aohi, whi + O_Woh, h2, 256, 512, 512,
                                              boh, h1, nullptr, nullptr, nullptr, nullptr, 0, nullptr);
    bn_part<<<64, 256, 0, s2>>>(h2);
    bn_fin<<<16, 256, 0, s2>>>(bn2_g, bn2_b);
    bn_apply_cvt<<<HTOT / 4 / 256, 256, 0, s2>>>(h2, nullptr, xhhi);
    tc_gemm<2, 0><<<dim3(32, 2), 256, 0, s2>>>(xhhi, whi + O_fh13, nullptr, 256, 4096, 512,
                                               nullptr, nullptr, nullptr, shhi, nullptr, nullptr, 0, nullptr);
    tc_gemm<0, 0><<<dim3(4, 2), 256, 0, s2>>>(shhi, whi + O_fh2, out, 256, 512, 2048,
                                              nullptr, h2, nullptr, nullptr, nullptr, nullptr, 0, nullptr);
    cudaEventRecord(evJoin, s2);

    // ---- NULL: batch-0 compacted FFN chain ----
    cudaStreamWaitEvent(0, evW2, 0);
    ln_cvt_h<<<CROWS, 128>>>(e2c, e1hi, ln2_g, ln2_b);   // e1hi reused as compacted xe (b0)
    tc_gemm<2, 0><<<dim3(32, CTILES), 256>>>(e1hi, whi + O_fe13, nullptr, CPAD, 4096, 512,
                                             nullptr, nullptr, nullptr, Shi, nullptr, nullptr, 0, nullptr);
    tc_gemm<0, 1><<<dim3(4, CTILES), 256>>>(Shi, whi + O_fe2, out + HTOT, CPAD, 512, 2048,
                                            nullptr, nullptr, e2c, nullptr, nullptr, nullptr, 0, rmap);
    sym_expand<<<(int)((ETOT / 2 / 4) / 256), 256>>>(out + HTOT);

    // ---- s3: batch-1 compacted FFN chain ----
    cudaStreamWaitEvent(s3, evE2, 0);
    cudaStreamWaitEvent(s3, evW2, 0);
    ln_cvt_h<<<CROWS, 128, 0, s3>>>(e2c + cOfs, e1hi + cOfs, ln2_g, ln2_b);
    tc_gemm<2, 0><<<dim3(32, CTILES), 256, 0, s3>>>(e1hi + cOfs, whi + O_fe13, nullptr, CPAD, 4096, 512,
                                                    nullptr, nullptr, nullptr, Shi + sOfs, nullptr, nullptr, 0, nullptr);
    tc_gemm<0, 1><<<dim3(4, CTILES), 256, 0, s3>>>(Shi + sOfs, whi + O_fe2, out + HTOT, CPAD, 512, 2048,
                                                   nullptr, nullptr, e2c + cOfs, nullptr, nullptr, nullptr, 0, rmap + CPAD);
    sym_expand<<<(int)((ETOT / 2 / 4) / 256), 256, 0, s3>>>(out + HTOT + eOut);
    cudaEventRecord(evB1, s3);

    // ---- join ----
    cudaStreamWaitEvent(0, evJoin, 0);
    cudaStreamWaitEvent(0, evB1, 0);
}